// round 3
// baseline (speedup 1.0000x reference)
#include <cuda_runtime.h>
#include <math.h>

#define NMAX 50000
#define EMAX 400000

// ---- scratch (device globals; no allocation allowed) ----
__device__ float g_ref_accum[NMAX * 4];   // sum x,y,z + count
__device__ float g_ref_vec[NMAX * 3];
__device__ float g_sproj[(size_t)NMAX * 192];
__device__ float g_geom[(size_t)EMAX * 8];

// ---------------- helpers ----------------
typedef unsigned long long u64;
__device__ __forceinline__ u64 pk2(float lo, float hi) {
    u64 r;
    asm("mov.b64 %0, {%1, %2};" : "=l"(r) : "f"(lo), "f"(hi));
    return r;
}
__device__ __forceinline__ void upk2(u64 v, float& lo, float& hi) {
    asm("mov.b64 {%0, %1}, %2;" : "=f"(lo), "=f"(hi) : "l"(v));
}
__device__ __forceinline__ u64 ffma2(u64 a, u64 b, u64 c) {
    u64 d;
    asm("fma.rn.f32x2 %0, %1, %2, %3;" : "=l"(d) : "l"(a), "l"(b), "l"(c));
    return d;
}
__device__ __forceinline__ u64 add2(u64 a, u64 b) {
    u64 d;
    asm("add.rn.f32x2 %0, %1, %2;" : "=l"(d) : "l"(a), "l"(b));
    return d;
}
__device__ __forceinline__ float tanh_fast(float x) {
    float y;
    asm("tanh.approx.f32 %0, %1;" : "=f"(y) : "f"(x));
    return y;
}
__device__ __forceinline__ void red2(float* a, float x, float y) {
    asm volatile("red.global.add.v2.f32 [%0], {%1, %2};"
                 :: "l"(a), "f"(x), "f"(y) : "memory");
}
__device__ __forceinline__ void red4(float* a, float x, float y, float z, float w) {
    asm volatile("red.global.add.v4.f32 [%0], {%1, %2, %3, %4};"
                 :: "l"(a), "f"(x), "f"(y), "f"(z), "f"(w) : "memory");
}

// ================= kernel 1: zero output + accumulators (float4) =================
__global__ void k_zero(float4* __restrict__ out4, int n_out4, int n_acc4) {
    float4* acc4 = (float4*)g_ref_accum;
    int total = n_out4 + n_acc4;
    float4 z = make_float4(0.f, 0.f, 0.f, 0.f);
    for (int i = blockIdx.x * blockDim.x + threadIdx.x; i < total;
         i += gridDim.x * blockDim.x) {
        if (i < n_out4) out4[i] = z;
        else acc4[i - n_out4] = z;
    }
}

// ================= kernel 2: segment-sum of edge_udiff over i =================
__global__ void k_refaccum(const float* __restrict__ ud,
                           const int* __restrict__ eidx, int E) {
    int e = blockIdx.x * blockDim.x + threadIdx.x;
    if (e >= E) return;
    int i = eidx[E + e];
    red4(&g_ref_accum[i * 4], ud[e * 3 + 0], ud[e * 3 + 1], ud[e * 3 + 2], 1.0f);
}

// ================= kernel 3: normalize ref vector per node =================
__global__ void k_refvec(int N) {
    int n = blockIdx.x * blockDim.x + threadIdx.x;
    if (n >= N) return;
    float4 a = *(const float4*)&g_ref_accum[n * 4];
    float ic = 1.0f / fmaxf(a.w, 1.0f);
    float rx = a.x * ic, ry = a.y * ic, rz = a.z * ic;
    float norm = sqrtf(rx * rx + ry * ry + rz * rz + 1e-9f);
    float inm = 1.0f / norm;
    rx *= inm; ry *= inm; rz *= inm;
    if (norm < 5e-5f) { rx = 1.0f; ry = 0.0f; rz = 0.0f; }
    g_ref_vec[n * 3 + 0] = rx;
    g_ref_vec[n * 3 + 1] = ry;
    g_ref_vec[n * 3 + 2] = rz;
}

// ================= kernel 4: node scalar MLP projection =================
__global__ void __launch_bounds__(256)
k_sproj(const float* __restrict__ ns, const float* __restrict__ W1,
        const float* __restrict__ b1, const float* __restrict__ W2,
        const float* __restrict__ b2, int N) {
    __shared__ float sW1[64 * 32];
    __shared__ float sW2[32 * 192];
    int tid = threadIdx.x;
    for (int q = tid; q < 64 * 32; q += 256) sW1[q] = W1[q];
    for (int q = tid; q < 32 * 192; q += 256) sW2[q] = W2[q];
    __syncthreads();
    const u64* sW2u = (const u64*)sW2;
    const float2* b2p = (const float2*)b2;
    int lane = tid & 31, warp = tid >> 5;

    u64 bb[3];
#pragma unroll
    for (int k = 0; k < 3; k++) {
        float2 t = b2p[lane + 32 * k];
        bb[k] = pk2(t.x, t.y);
    }
    float b1v = b1[lane];

    int npairs = (N + 1) >> 1;
    for (int p = blockIdx.x * 8 + warp; p < npairs; p += gridDim.x * 8) {
        int nA = p * 2;
        int nB = min(nA + 1, N - 1);
        float aA0 = ns[(size_t)nA * 64 + lane], aA1 = ns[(size_t)nA * 64 + 32 + lane];
        float aB0 = ns[(size_t)nB * 64 + lane], aB1 = ns[(size_t)nB * 64 + 32 + lane];
        float tA = b1v, tB = b1v;
#pragma unroll
        for (int r = 0; r < 64; r++) {
            float w = sW1[r * 32 + lane];
            float vA = __shfl_sync(0xffffffffu, (r < 32) ? aA0 : aA1, r & 31);
            float vB = __shfl_sync(0xffffffffu, (r < 32) ? aB0 : aB1, r & 31);
            tA = fmaf(vA, w, tA);
            tB = fmaf(vB, w, tB);
        }
        tA = __fdividef(tA, 1.0f + __expf(-tA)) * (1.0f / 0.6f);
        tB = __fdividef(tB, 1.0f + __expf(-tB)) * (1.0f / 0.6f);
        u64 oA[3], oB[3];
#pragma unroll
        for (int k = 0; k < 3; k++) { oA[k] = bb[k]; oB[k] = bb[k]; }
#pragma unroll
        for (int r = 0; r < 32; r++) {
            u64 w0 = sW2u[r * 96 + lane];
            u64 w1 = sW2u[r * 96 + 32 + lane];
            u64 w2 = sW2u[r * 96 + 64 + lane];
            float vA = __shfl_sync(0xffffffffu, tA, r);
            float vB = __shfl_sync(0xffffffffu, tB, r);
            u64 vvA = pk2(vA, vA), vvB = pk2(vB, vB);
            oA[0] = ffma2(vvA, w0, oA[0]);
            oA[1] = ffma2(vvA, w1, oA[1]);
            oA[2] = ffma2(vvA, w2, oA[2]);
            oB[0] = ffma2(vvB, w0, oB[0]);
            oB[1] = ffma2(vvB, w1, oB[1]);
            oB[2] = ffma2(vvB, w2, oB[2]);
        }
        u64* outA = (u64*)g_sproj + (size_t)nA * 96;
#pragma unroll
        for (int k = 0; k < 3; k++) outA[lane + 32 * k] = oA[k];
        if (nB != nA) {
            u64* outB = (u64*)g_sproj + (size_t)nB * 96;
#pragma unroll
            for (int k = 0; k < 3; k++) outB[lane + 32 * k] = oB[k];
        }
    }
}

// ================= spherical-harmonic invariants (streamed) =================
__device__ __forceinline__ void sh_invariants(
    float xe, float ye, float ze, float xr, float yr, float zr, float* inv) {
    float nne = rsqrtf(xe * xe + ye * ye + ze * ze + 1e-12f);
    xe *= nne; ye *= nne; ze *= nne;
    float nnr = rsqrtf(xr * xr + yr * yr + zr * zr + 1e-12f);
    xr *= nnr; yr *= nnr; zr *= nnr;
    float st2e = xe * xe + ye * ye;
    float st2r = xr * xr + yr * yr;
    float ste = sqrtf(st2e), str = sqrtf(st2r);
    float c1e = (st2e > 0.0f) ? xe / ste : 0.0f;
    float s1e = (st2e > 0.0f) ? ye / ste : 0.0f;
    float c1r = (st2r > 0.0f) ? xr / str : 0.0f;
    float s1r = (st2r > 0.0f) ? yr / str : 0.0f;

    float acc[7];
#pragma unroll
    for (int l = 0; l < 7; l++) acc[l] = 0.0f;

    float de = 0.28209479177387814f, dr = 0.28209479177387814f;
    float ce = 1.0f, se = 0.0f, cr = 1.0f, sr = 0.0f;
#pragma unroll
    for (int m = 0; m <= 6; m++) {
        if (m > 0) {
            float km = sqrtf((2.0f * m + 1.0f) / (2.0f * m));
            de = -km * ste * de;
            dr = -km * str * dr;
            float ce2 = c1e * ce - s1e * se; se = s1e * ce + c1e * se; ce = ce2;
            float cr2 = c1r * cr - s1r * sr; sr = s1r * cr + c1r * sr; cr = cr2;
        }
        float w = (m == 0) ? 1.0f : 2.0f * (ce * cr + se * sr);
        float pe1 = de, pr1 = dr;
        acc[m] += w * pe1 * pr1;
        if (m < 6) {
            float kp = sqrtf(2.0f * m + 3.0f);
            float pe = kp * ze * de;
            float pr = kp * zr * dr;
            acc[m + 1] += w * pe * pr;
            float pe0 = pe1, pr0 = pr1;
#pragma unroll
            for (int l = m + 2; l <= 6; l++) {
                float fl = (float)l;
                float a = sqrtf((4.0f * fl * fl - 1.0f) / (fl * fl - (float)(m * m)));
                float b = sqrtf(((fl - 1.0f) * (fl - 1.0f) - (float)(m * m)) /
                                (4.0f * (fl - 1.0f) * (fl - 1.0f) - 1.0f));
                float pen = a * (ze * pe - b * pe0); pe0 = pe; pe = pen;
                float prn = a * (zr * pr - b * pr0); pr0 = pr; pr = prn;
                acc[l] += w * pe * pr;
            }
        }
    }
    const float fourpi = 12.566370614359172f;
#pragma unroll
    for (int l = 0; l < 7; l++) inv[l] = acc[l] * (fourpi / (2.0f * l + 1.0f));
}

// ================= kernel 5: per-edge geometric features =================
__global__ void k_geom(const float* __restrict__ ud, const int* __restrict__ eidx,
                       const float* __restrict__ ln_g, const float* __restrict__ ln_b,
                       int E) {
    int e = blockIdx.x * blockDim.x + threadIdx.x;
    if (e >= E) return;
    float ux = ud[e * 3 + 0], uy = ud[e * 3 + 1], uz = ud[e * 3 + 2];
    int i = __ldg(&eidx[E + e]);
    float rx = __ldg(&g_ref_vec[i * 3 + 0]);
    float ry = __ldg(&g_ref_vec[i * 3 + 1]);
    float rz = __ldg(&g_ref_vec[i * 3 + 2]);
    float inv[7];
    sh_invariants(ux, uy, uz, rx, ry, rz, inv);
    float mu = 0.0f;
#pragma unroll
    for (int l = 0; l < 7; l++) mu += inv[l];
    mu *= (1.0f / 7.0f);
    float var = 0.0f;
#pragma unroll
    for (int l = 0; l < 7; l++) { float d = inv[l] - mu; var += d * d; }
    var *= (1.0f / 7.0f);
    float isd = rsqrtf(var + 1e-5f);
    float o[8];
    o[0] = ux * rx + uy * ry + uz * rz;
#pragma unroll
    for (int l = 0; l < 7; l++)
        o[1 + l] = (inv[l] - mu) * isd * ln_g[l] + ln_b[l];
    float4* gg = (float4*)(g_geom + (size_t)e * 8);
    gg[0] = make_float4(o[0], o[1], o[2], o[3]);
    gg[1] = make_float4(o[4], o[5], o[6], o[7]);
}

// ================= kernel 6: main — block GEMM + fused epilogue =================
// 384 threads, tile = 64 edges x 192 cols. Thread = 4 edges x 8 cols (4 u64).
// eg = tid&15 (edge group of 4), cg = tid>>4 (col group of 8 scalar cols).
#define ACC_STRIDE 97

__global__ void __launch_bounds__(384, 2)
k_main(const float* __restrict__ rbf, const float* __restrict__ ud,
       const int* __restrict__ eidx, const float* __restrict__ W_edge,
       const float* __restrict__ b_edge, const float* __restrict__ W_inv,
       const float* __restrict__ b_inv, const float* __restrict__ nv,
       float* __restrict__ out, int N, int E) {
    extern __shared__ float dsm[];
    float* sWe = dsm;                                   // 64*192 f = 48KB
    float* sWinv = dsm + 64 * 192;                      // 8*192 f = 6KB
    u64* sAcc = (u64*)(sWinv + 8 * 192);                // 64*97 u64 = 49.7KB
    float4* sXbuf = (float4*)(sAcc + 64 * ACC_STRIDE);  // 12 warps * 32 f4 = 6KB

    int tid = threadIdx.x;
    for (int q = tid; q < 64 * 192 / 4; q += 384)
        ((float4*)sWe)[q] = ((const float4*)W_edge)[q];
    for (int q = tid; q < 8 * 192 / 4; q += 384)
        ((float4*)sWinv)[q] = ((const float4*)W_inv)[q];
    __syncthreads();

    int lane = tid & 31, warp = tid >> 5;
    int eg = tid & 15, cg = tid >> 4;  // cg in 0..23
    const ulonglong2* sWeV = (const ulonglong2*)sWe;  // index: k*48 + cg*2
    const u64* sWinv64 = (const u64*)sWinv;           // index: q*96 + m

    float* outv = out + (size_t)N * 64;
    float4* xwarp = &sXbuf[warp * 32];

    u64 be2[3], bi2[3];
    const float2* be2p = (const float2*)b_edge;
    const float2* bi2p = (const float2*)b_inv;
#pragma unroll
    for (int k = 0; k < 3; k++) {
        float2 t = be2p[lane + 32 * k]; be2[k] = pk2(t.x, t.y);
        float2 u = bi2p[lane + 32 * k]; bi2[k] = pk2(u.x, u.y);
    }
    const float2* sp2 = (const float2*)g_sproj;

    const float inv_sqrt3 = 0.57735026918962576f;
    const float ish = 0.125f;

    int ntiles = (E + 63) >> 6;
    for (int t = blockIdx.x; t < ntiles; t += gridDim.x) {
        int e0 = t * 64;
        int ecnt = min(64, E - e0);

        // ---------- Phase 1: GEMM (acc = rbf_tile @ W_edge) ----------
        u64 acc[4][4];
#pragma unroll
        for (int r = 0; r < 4; r++)
#pragma unroll
            for (int n = 0; n < 4; n++) acc[r][n] = 0ull;

        size_t eb[4];
#pragma unroll
        for (int r = 0; r < 4; r++) {
            int e = e0 + eg * 4 + r;
            eb[r] = (size_t)min(e, E - 1) * 64;
        }

#pragma unroll 4
        for (int kb = 0; kb < 64; kb += 4) {
            float4 a0 = __ldg((const float4*)(rbf + eb[0] + kb));
            float4 a1 = __ldg((const float4*)(rbf + eb[1] + kb));
            float4 a2 = __ldg((const float4*)(rbf + eb[2] + kb));
            float4 a3 = __ldg((const float4*)(rbf + eb[3] + kb));
#pragma unroll
            for (int j = 0; j < 4; j++) {
                ulonglong2 bA = sWeV[(kb + j) * 48 + cg * 2];
                ulonglong2 bB = sWeV[(kb + j) * 48 + cg * 2 + 1];
                float v0 = (j == 0) ? a0.x : (j == 1) ? a0.y : (j == 2) ? a0.z : a0.w;
                float v1 = (j == 0) ? a1.x : (j == 1) ? a1.y : (j == 2) ? a1.z : a1.w;
                float v2 = (j == 0) ? a2.x : (j == 1) ? a2.y : (j == 2) ? a2.z : a2.w;
                float v3 = (j == 0) ? a3.x : (j == 1) ? a3.y : (j == 2) ? a3.z : a3.w;
                u64 d0 = pk2(v0, v0), d1 = pk2(v1, v1);
                u64 d2 = pk2(v2, v2), d3 = pk2(v3, v3);
                acc[0][0] = ffma2(d0, bA.x, acc[0][0]);
                acc[0][1] = ffma2(d0, bA.y, acc[0][1]);
                acc[0][2] = ffma2(d0, bB.x, acc[0][2]);
                acc[0][3] = ffma2(d0, bB.y, acc[0][3]);
                acc[1][0] = ffma2(d1, bA.x, acc[1][0]);
                acc[1][1] = ffma2(d1, bA.y, acc[1][1]);
                acc[1][2] = ffma2(d1, bB.x, acc[1][2]);
                acc[1][3] = ffma2(d1, bB.y, acc[1][3]);
                acc[2][0] = ffma2(d2, bA.x, acc[2][0]);
                acc[2][1] = ffma2(d2, bA.y, acc[2][1]);
                acc[2][2] = ffma2(d2, bB.x, acc[2][2]);
                acc[2][3] = ffma2(d2, bB.y, acc[2][3]);
                acc[3][0] = ffma2(d3, bA.x, acc[3][0]);
                acc[3][1] = ffma2(d3, bA.y, acc[3][1]);
                acc[3][2] = ffma2(d3, bB.x, acc[3][2]);
                acc[3][3] = ffma2(d3, bB.y, acc[3][3]);
            }
        }

        // sync: also guarantees previous tile's Phase 3 readers are done
        __syncthreads();

        // ---------- Phase 2: stage acc to smem ----------
#pragma unroll
        for (int r = 0; r < 4; r++) {
            int el = eg * 4 + r;
            u64* dst = &sAcc[el * ACC_STRIDE + cg * 4];
            dst[0] = acc[r][0]; dst[1] = acc[r][1];
            dst[2] = acc[r][2]; dst[3] = acc[r][3];
        }
        __syncthreads();

        // ---------- Phase 3: per-edge epilogue (warp per edge pair) ----------
        for (int p = warp * 2; p < 64; p += 24) {
            int elA = p, elB = p + 1;
            if (elA >= ecnt) continue;
            bool hasB = (elB < ecnt);
            int eA = e0 + elA, eB = hasB ? (e0 + elB) : eA;
            int jA = __ldg(&eidx[eA]), iA = __ldg(&eidx[E + eA]);
            int jB = __ldg(&eidx[eB]), iB = __ldg(&eidx[E + eB]);

            float4 gA0 = *(const float4*)(g_geom + (size_t)eA * 8);
            float4 gA1 = *(const float4*)(g_geom + (size_t)eA * 8 + 4);
            float4 gB0 = *(const float4*)(g_geom + (size_t)eB * 8);
            float4 gB1 = *(const float4*)(g_geom + (size_t)eB * 8 + 4);
            u64 gpA[8], gpB[8];
            gpA[0] = pk2(gA0.x, gA0.x); gpA[1] = pk2(gA0.y, gA0.y);
            gpA[2] = pk2(gA0.z, gA0.z); gpA[3] = pk2(gA0.w, gA0.w);
            gpA[4] = pk2(gA1.x, gA1.x); gpA[5] = pk2(gA1.y, gA1.y);
            gpA[6] = pk2(gA1.z, gA1.z); gpA[7] = pk2(gA1.w, gA1.w);
            gpB[0] = pk2(gB0.x, gB0.x); gpB[1] = pk2(gB0.y, gB0.y);
            gpB[2] = pk2(gB0.z, gB0.z); gpB[3] = pk2(gB0.w, gB0.w);
            gpB[4] = pk2(gB1.x, gB1.x); gpB[5] = pk2(gB1.y, gB1.y);
            gpB[6] = pk2(gB1.z, gB1.z); gpB[7] = pk2(gB1.w, gB1.w);

            float xvA[6], xvB[6];
#pragma unroll
            for (int k2 = 0; k2 < 3; k2++) {
                int m = lane + 32 * k2;
                u64 gA = bi2[k2], gB = bi2[k2];
#pragma unroll
                for (int q = 0; q < 8; q++) {
                    u64 w = sWinv64[q * 96 + m];
                    gA = ffma2(gpA[q], w, gA);
                    gB = ffma2(gpB[q], w, gB);
                }
                float gA0f, gA1f, gB0f, gB1f;
                upk2(gA, gA0f, gA1f);
                upk2(gB, gB0f, gB1f);
                float sA0 = __fdividef(gA0f, 1.0f + __expf(-gA0f)) * (1.0f / 0.6f);
                float sA1 = __fdividef(gA1f, 1.0f + __expf(-gA1f)) * (1.0f / 0.6f);
                float sB0 = __fdividef(gB0f, 1.0f + __expf(-gB0f)) * (1.0f / 0.6f);
                float sB1 = __fdividef(gB1f, 1.0f + __expf(-gB1f)) * (1.0f / 0.6f);
                float fA0 = 1.0f + tanh_fast(sA0);
                float fA1 = 1.0f + tanh_fast(sA1);
                float fB0 = 1.0f + tanh_fast(sB0);
                float fB1 = 1.0f + tanh_fast(sB1);
                u64 rhA = add2(sAcc[elA * ACC_STRIDE + m], be2[k2]);
                u64 rhB = add2(sAcc[elB * ACC_STRIDE + (hasB ? m : 0)], be2[k2]);
                float rA0, rA1, rB0, rB1;
                upk2(rhA, rA0, rA1);
                upk2(rhB, rB0, rB1);
                float2 spA = __ldg(&sp2[(size_t)jA * 96 + m]);
                float2 spB = __ldg(&sp2[(size_t)jB * 96 + m]);
                xvA[2 * k2 + 0] = spA.x * rA0 * fA0 * inv_sqrt3;
                xvA[2 * k2 + 1] = spA.y * rA1 * fA1 * inv_sqrt3;
                xvB[2 * k2 + 0] = spB.x * rB0 * fB0 * inv_sqrt3;
                xvB[2 * k2 + 1] = spB.y * rB1 * fB1 * inv_sqrt3;
            }

            // ---- scatter edge A ----
            {
                red2(&out[(size_t)iA * 64 + 2 * lane], xvA[4], xvA[5]);
                xwarp[lane] = make_float4(xvA[0], xvA[2], xvA[1], xvA[3]);
                __syncwarp();
                float u0 = ud[eA * 3 + 0], u1 = ud[eA * 3 + 1], u2 = ud[eA * 3 + 2];
                const float4* xp4 = (const float4*)xwarp;
                {
                    int o = 4 * lane;
                    int q = o & 63;
                    float udd = (o >> 6) ? u1 : u0;
                    float4 pa = xp4[q >> 1], pb = xp4[(q >> 1) + 1];
                    float4 nvv = *(const float4*)(nv + (size_t)jA * 192 + o);
                    red4(&outv[(size_t)iA * 192 + o],
                         (pa.x * nvv.x + pa.y * udd) * ish,
                         (pa.z * nvv.y + pa.w * udd) * ish,
                         (pb.x * nvv.z + pb.y * udd) * ish,
                         (pb.z * nvv.w + pb.w * udd) * ish);
                }
                if (lane < 16) {
                    int o = 128 + 4 * lane;
                    int q = 4 * lane;
                    float4 pa = xp4[q >> 1], pb = xp4[(q >> 1) + 1];
                    float4 nvv = *(const float4*)(nv + (size_t)jA * 192 + o);
                    red4(&outv[(size_t)iA * 192 + o],
                         (pa.x * nvv.x + pa.y * u2) * ish,
                         (pa.z * nvv.y + pa.w * u2) * ish,
                         (pb.x * nvv.z + pb.y * u2) * ish,
                         (pb.z * nvv.w + pb.w * u2) * ish);
                }
                __syncwarp();
            }
            // ---- scatter edge B ----
            if (hasB) {
                red2(&out[(size_t)iB * 64 + 2 * lane], xvB[4], xvB[5]);
                xwarp[lane] = make_float4(xvB[0], xvB[2], xvB[1], xvB[3]);
                __syncwarp();
                float u0 = ud[eB * 3 + 0], u1 = ud[eB * 3 + 1], u2 = ud[eB * 3 + 2];
                const float4* xp4 = (const float4*)xwarp;
                {
                    int o = 4 * lane;
                    int q = o & 63;
                    float udd = (o >> 6) ? u1 : u0;
                    float4 pa = xp4[q >> 1], pb = xp4[(q >> 1) + 1];
                    float4 nvv = *(const float4*)(nv + (size_t)jB * 192 + o);
                    red4(&outv[(size_t)iB * 192 + o],
                         (pa.x * nvv.x + pa.y * udd) * ish,
                         (pa.z * nvv.y + pa.w * udd) * ish,
                         (pb.x * nvv.z + pb.y * udd) * ish,
                         (pb.z * nvv.w + pb.w * udd) * ish);
                }
                if (lane < 16) {
                    int o = 128 + 4 * lane;
                    int q = 4 * lane;
                    float4 pa = xp4[q >> 1], pb = xp4[(q >> 1) + 1];
                    float4 nvv = *(const float4*)(nv + (size_t)jB * 192 + o);
                    red4(&outv[(size_t)iB * 192 + o],
                         (pa.x * nvv.x + pa.y * u2) * ish,
                         (pa.z * nvv.y + pa.w * u2) * ish,
                         (pb.x * nvv.z + pb.y * u2) * ish,
                         (pb.z * nvv.w + pb.w * u2) * ish);
                }
                __syncwarp();
            }
        }
    }
}

// ================= launch =================
extern "C" void kernel_launch(void* const* d_in, const int* in_sizes, int n_in,
                              void* d_out, int out_size) {
    const float* node_scalar = (const float*)d_in[0];
    const float* node_vector = (const float*)d_in[1];
    const float* edge_rbf    = (const float*)d_in[2];
    const float* edge_udiff  = (const float*)d_in[3];
    const int*   edge_index  = (const int*)d_in[4];
    const float* W_edge      = (const float*)d_in[5];
    const float* b_edge      = (const float*)d_in[6];
    const float* W_x1        = (const float*)d_in[7];
    const float* b_x1        = (const float*)d_in[8];
    const float* W_x2        = (const float*)d_in[9];
    const float* b_x2        = (const float*)d_in[10];
    const float* ln_g        = (const float*)d_in[11];
    const float* ln_b        = (const float*)d_in[12];
    const float* W_inv       = (const float*)d_in[13];
    const float* b_inv       = (const float*)d_in[14];

    int N = in_sizes[0] / 64;
    int E = in_sizes[3] / 3;
    float* out = (float*)d_out;

    int smem_main = 64 * 192 * 4 + 8 * 192 * 4 + 64 * ACC_STRIDE * 8 + 12 * 32 * 16;
    cudaFuncSetAttribute(k_main, cudaFuncAttributeMaxDynamicSharedMemorySize,
                         smem_main);

    k_zero<<<1024, 256>>>((float4*)out, out_size / 4, N);
    k_refaccum<<<(E + 255) / 256, 256>>>(edge_udiff, edge_index, E);
    k_refvec<<<(N + 255) / 256, 256>>>(N);
    k_sproj<<<296, 256>>>(node_scalar, W_x1, b_x1, W_x2, b_x2, N);
    k_geom<<<(E + 255) / 256, 256>>>(edge_udiff, edge_index, ln_g, ln_b, E);
    k_main<<<296, 384, smem_main>>>(edge_rbf, edge_udiff, edge_index, W_edge,
                                    b_edge, W_inv, b_inv, node_vector, out, N, E);
}

// round 4
// speedup vs baseline: 1.2946x; 1.2946x over previous
#include <cuda_runtime.h>
#include <math.h>

#define NMAX 50000
#define EMAX 400000

// ---- scratch (device globals; no allocation allowed) ----
__device__ float g_ref_accum[NMAX * 4];   // sum x,y,z + count
__device__ float g_ref_vec[NMAX * 3];
__device__ float g_sproj[(size_t)NMAX * 192];
__device__ float g_geom[(size_t)EMAX * 8];

// ---------------- helpers ----------------
typedef unsigned long long u64;
__device__ __forceinline__ u64 pk2(float lo, float hi) {
    u64 r;
    asm("mov.b64 %0, {%1, %2};" : "=l"(r) : "f"(lo), "f"(hi));
    return r;
}
__device__ __forceinline__ void upk2(u64 v, float& lo, float& hi) {
    asm("mov.b64 {%0, %1}, %2;" : "=f"(lo), "=f"(hi) : "l"(v));
}
__device__ __forceinline__ u64 ffma2(u64 a, u64 b, u64 c) {
    u64 d;
    asm("fma.rn.f32x2 %0, %1, %2, %3;" : "=l"(d) : "l"(a), "l"(b), "l"(c));
    return d;
}
__device__ __forceinline__ u64 mul2(u64 a, u64 b) {
    u64 d;
    asm("mul.rn.f32x2 %0, %1, %2;" : "=l"(d) : "l"(a), "l"(b));
    return d;
}
__device__ __forceinline__ float tanh_fast(float x) {
    float y;
    asm("tanh.approx.f32 %0, %1;" : "=f"(y) : "f"(x));
    return y;
}
__device__ __forceinline__ void red4(float* a, float x, float y, float z, float w) {
    asm volatile("red.global.add.v4.f32 [%0], {%1, %2, %3, %4};"
                 :: "l"(a), "f"(x), "f"(y), "f"(z), "f"(w) : "memory");
}

// ================= kernel 1: zero output + accumulators (float4) =================
__global__ void k_zero(float4* __restrict__ out4, int n_out4, int n_acc4) {
    float4* acc4 = (float4*)g_ref_accum;
    int total = n_out4 + n_acc4;
    float4 z = make_float4(0.f, 0.f, 0.f, 0.f);
    for (int i = blockIdx.x * blockDim.x + threadIdx.x; i < total;
         i += gridDim.x * blockDim.x) {
        if (i < n_out4) out4[i] = z;
        else acc4[i - n_out4] = z;
    }
}

// ================= kernel 2: segment-sum of edge_udiff over i =================
__global__ void k_refaccum(const float* __restrict__ ud,
                           const int* __restrict__ eidx, int E) {
    int e = blockIdx.x * blockDim.x + threadIdx.x;
    if (e >= E) return;
    int i = eidx[E + e];
    red4(&g_ref_accum[i * 4], ud[e * 3 + 0], ud[e * 3 + 1], ud[e * 3 + 2], 1.0f);
}

// ================= kernel 3: normalize ref vector per node =================
__global__ void k_refvec(int N) {
    int n = blockIdx.x * blockDim.x + threadIdx.x;
    if (n >= N) return;
    float4 a = *(const float4*)&g_ref_accum[n * 4];
    float ic = 1.0f / fmaxf(a.w, 1.0f);
    float rx = a.x * ic, ry = a.y * ic, rz = a.z * ic;
    float norm = sqrtf(rx * rx + ry * ry + rz * rz + 1e-9f);
    float inm = 1.0f / norm;
    rx *= inm; ry *= inm; rz *= inm;
    if (norm < 5e-5f) { rx = 1.0f; ry = 0.0f; rz = 0.0f; }
    g_ref_vec[n * 3 + 0] = rx;
    g_ref_vec[n * 3 + 1] = ry;
    g_ref_vec[n * 3 + 2] = rz;
}

// ================= kernel 4: node scalar MLP projection =================
__global__ void __launch_bounds__(256)
k_sproj(const float* __restrict__ ns, const float* __restrict__ W1,
        const float* __restrict__ b1, const float* __restrict__ W2,
        const float* __restrict__ b2, int N) {
    __shared__ float sW1[64 * 32];
    __shared__ float sW2[32 * 192];
    int tid = threadIdx.x;
    for (int q = tid; q < 64 * 32; q += 256) sW1[q] = W1[q];
    for (int q = tid; q < 32 * 192; q += 256) sW2[q] = W2[q];
    __syncthreads();
    const u64* sW2u = (const u64*)sW2;
    const float2* b2p = (const float2*)b2;
    int lane = tid & 31, warp = tid >> 5;

    u64 bb[3];
#pragma unroll
    for (int k = 0; k < 3; k++) {
        float2 t = b2p[lane + 32 * k];
        bb[k] = pk2(t.x, t.y);
    }
    float b1v = b1[lane];

    int npairs = (N + 1) >> 1;
    for (int p = blockIdx.x * 8 + warp; p < npairs; p += gridDim.x * 8) {
        int nA = p * 2;
        int nB = min(nA + 1, N - 1);
        float aA0 = ns[(size_t)nA * 64 + lane], aA1 = ns[(size_t)nA * 64 + 32 + lane];
        float aB0 = ns[(size_t)nB * 64 + lane], aB1 = ns[(size_t)nB * 64 + 32 + lane];
        float tA = b1v, tB = b1v;
#pragma unroll
        for (int r = 0; r < 64; r++) {
            float w = sW1[r * 32 + lane];
            float vA = __shfl_sync(0xffffffffu, (r < 32) ? aA0 : aA1, r & 31);
            float vB = __shfl_sync(0xffffffffu, (r < 32) ? aB0 : aB1, r & 31);
            tA = fmaf(vA, w, tA);
            tB = fmaf(vB, w, tB);
        }
        tA = __fdividef(tA, 1.0f + __expf(-tA)) * (1.0f / 0.6f);
        tB = __fdividef(tB, 1.0f + __expf(-tB)) * (1.0f / 0.6f);
        u64 oA[3], oB[3];
#pragma unroll
        for (int k = 0; k < 3; k++) { oA[k] = bb[k]; oB[k] = bb[k]; }
#pragma unroll
        for (int r = 0; r < 32; r++) {
            u64 w0 = sW2u[r * 96 + lane];
            u64 w1 = sW2u[r * 96 + 32 + lane];
            u64 w2 = sW2u[r * 96 + 64 + lane];
            float vA = __shfl_sync(0xffffffffu, tA, r);
            float vB = __shfl_sync(0xffffffffu, tB, r);
            u64 vvA = pk2(vA, vA), vvB = pk2(vB, vB);
            oA[0] = ffma2(vvA, w0, oA[0]);
            oA[1] = ffma2(vvA, w1, oA[1]);
            oA[2] = ffma2(vvA, w2, oA[2]);
            oB[0] = ffma2(vvB, w0, oB[0]);
            oB[1] = ffma2(vvB, w1, oB[1]);
            oB[2] = ffma2(vvB, w2, oB[2]);
        }
        u64* outA = (u64*)g_sproj + (size_t)nA * 96;
#pragma unroll
        for (int k = 0; k < 3; k++) outA[lane + 32 * k] = oA[k];
        if (nB != nA) {
            u64* outB = (u64*)g_sproj + (size_t)nB * 96;
#pragma unroll
            for (int k = 0; k < 3; k++) outB[lane + 32 * k] = oB[k];
        }
    }
}

// ================= spherical-harmonic invariants (streamed) =================
__device__ __forceinline__ void sh_invariants(
    float xe, float ye, float ze, float xr, float yr, float zr, float* inv) {
    float nne = rsqrtf(xe * xe + ye * ye + ze * ze + 1e-12f);
    xe *= nne; ye *= nne; ze *= nne;
    float nnr = rsqrtf(xr * xr + yr * yr + zr * zr + 1e-12f);
    xr *= nnr; yr *= nnr; zr *= nnr;
    float st2e = xe * xe + ye * ye;
    float st2r = xr * xr + yr * yr;
    float ste = sqrtf(st2e), str = sqrtf(st2r);
    float c1e = (st2e > 0.0f) ? xe / ste : 0.0f;
    float s1e = (st2e > 0.0f) ? ye / ste : 0.0f;
    float c1r = (st2r > 0.0f) ? xr / str : 0.0f;
    float s1r = (st2r > 0.0f) ? yr / str : 0.0f;

    float acc[7];
#pragma unroll
    for (int l = 0; l < 7; l++) acc[l] = 0.0f;

    float de = 0.28209479177387814f, dr = 0.28209479177387814f;
    float ce = 1.0f, se = 0.0f, cr = 1.0f, sr = 0.0f;
#pragma unroll
    for (int m = 0; m <= 6; m++) {
        if (m > 0) {
            float km = sqrtf((2.0f * m + 1.0f) / (2.0f * m));
            de = -km * ste * de;
            dr = -km * str * dr;
            float ce2 = c1e * ce - s1e * se; se = s1e * ce + c1e * se; ce = ce2;
            float cr2 = c1r * cr - s1r * sr; sr = s1r * cr + c1r * sr; cr = cr2;
        }
        float w = (m == 0) ? 1.0f : 2.0f * (ce * cr + se * sr);
        float pe1 = de, pr1 = dr;
        acc[m] += w * pe1 * pr1;
        if (m < 6) {
            float kp = sqrtf(2.0f * m + 3.0f);
            float pe = kp * ze * de;
            float pr = kp * zr * dr;
            acc[m + 1] += w * pe * pr;
            float pe0 = pe1, pr0 = pr1;
#pragma unroll
            for (int l = m + 2; l <= 6; l++) {
                float fl = (float)l;
                float a = sqrtf((4.0f * fl * fl - 1.0f) / (fl * fl - (float)(m * m)));
                float b = sqrtf(((fl - 1.0f) * (fl - 1.0f) - (float)(m * m)) /
                                (4.0f * (fl - 1.0f) * (fl - 1.0f) - 1.0f));
                float pen = a * (ze * pe - b * pe0); pe0 = pe; pe = pen;
                float prn = a * (zr * pr - b * pr0); pr0 = pr; pr = prn;
                acc[l] += w * pe * pr;
            }
        }
    }
    const float fourpi = 12.566370614359172f;
#pragma unroll
    for (int l = 0; l < 7; l++) inv[l] = acc[l] * (fourpi / (2.0f * l + 1.0f));
}

// ================= kernel 5: per-edge geometric features =================
__global__ void k_geom(const float* __restrict__ ud, const int* __restrict__ eidx,
                       const float* __restrict__ ln_g, const float* __restrict__ ln_b,
                       int E) {
    int e = blockIdx.x * blockDim.x + threadIdx.x;
    if (e >= E) return;
    float ux = ud[e * 3 + 0], uy = ud[e * 3 + 1], uz = ud[e * 3 + 2];
    int i = __ldg(&eidx[E + e]);
    float rx = __ldg(&g_ref_vec[i * 3 + 0]);
    float ry = __ldg(&g_ref_vec[i * 3 + 1]);
    float rz = __ldg(&g_ref_vec[i * 3 + 2]);
    float inv[7];
    sh_invariants(ux, uy, uz, rx, ry, rz, inv);
    float mu = 0.0f;
#pragma unroll
    for (int l = 0; l < 7; l++) mu += inv[l];
    mu *= (1.0f / 7.0f);
    float var = 0.0f;
#pragma unroll
    for (int l = 0; l < 7; l++) { float d = inv[l] - mu; var += d * d; }
    var *= (1.0f / 7.0f);
    float isd = rsqrtf(var + 1e-5f);
    float o[8];
    o[0] = ux * rx + uy * ry + uz * rz;
#pragma unroll
    for (int l = 0; l < 7; l++)
        o[1 + l] = (inv[l] - mu) * isd * ln_g[l] + ln_b[l];
    float4* gg = (float4*)(g_geom + (size_t)e * 8);
    gg[0] = make_float4(o[0], o[1], o[2], o[3]);
    gg[1] = make_float4(o[4], o[5], o[6], o[7]);
}

// ================= kernel 6: main — k-packed GEMV + fused epilogue =================
// Warp-pair owns 8-edge tiles. Each warp: 3 scalar cols per lane.
//   warp0 cols: lane, lane+64, lane+128    (h-range 0..31)
//   warp1 cols: lane+32, lane+96, lane+160 (h-range 32..63)
// acc is packed over k: acc u64 = [sum even-k, sum odd-k]; final = lo+hi.
#define WT64 33   // u64 stride per column of transposed W_edge

__global__ void __launch_bounds__(256, 2)
k_main(const float* __restrict__ rbf, const float* __restrict__ ud,
       const int* __restrict__ eidx, const float* __restrict__ W_edge,
       const float* __restrict__ b_edge, const float* __restrict__ W_inv,
       const float* __restrict__ b_inv, const float* __restrict__ nv,
       float* __restrict__ out, int N, int E) {
    extern __shared__ float dsm[];
    float* sWt = dsm;                 // 192 cols * 66 floats = 49.5KB (k-major)
    float* sX = dsm + 192 * 66;       // 8 warps * 128 floats = 4KB

    int tid = threadIdx.x;
    // transpose W_edge: sWt[c*66 + k] = W_edge[k*192 + c]
    for (int idx = tid; idx < 64 * 192; idx += 256) {
        int k = idx / 192, c = idx - k * 192;
        sWt[c * 66 + k] = W_edge[idx];
    }
    __syncthreads();
    const u64* sWt64 = (const u64*)sWt;  // col c: sWt64[c*33 + kp]

    int lane = tid & 31, warp = tid >> 5;
    int w01 = warp & 1, pairId = warp >> 1;
    float* xw = sX + warp * 128;

    int c0 = lane + 32 * w01;  // x1 col (h = c0)
    int wtb0 = c0 * WT64, wtb1 = (c0 + 64) * WT64, wtb2 = (c0 + 128) * WT64;

    // persistent packed W_inv: wiv[j][qp] = [W_inv[2qp][c], W_inv[2qp+1][c]]
    u64 wiv[3][4];
#pragma unroll
    for (int j = 0; j < 3; j++) {
        int c = c0 + 64 * j;
#pragma unroll
        for (int qp = 0; qp < 4; qp++)
            wiv[j][qp] = pk2(__ldg(&W_inv[(2 * qp) * 192 + c]),
                             __ldg(&W_inv[(2 * qp + 1) * 192 + c]));
    }
    float binv[3], bedg[3];
#pragma unroll
    for (int j = 0; j < 3; j++) {
        binv[j] = __ldg(&b_inv[c0 + 64 * j]);
        bedg[j] = __ldg(&b_edge[c0 + 64 * j]);
    }

    float* outv = out + (size_t)N * 64;
    const float inv_sqrt3 = 0.57735026918962576f;
    const float ish = 0.125f;
    int hb = 32 * w01;

    int ntiles = (E + 7) >> 3;
    for (int t = blockIdx.x * 4 + pairId; t < ntiles; t += gridDim.x * 4) {
        int e0 = t * 8;
        int ecnt = min(8, E - e0);

        u64 acc[8][3];
#pragma unroll
        for (int s = 0; s < 8; s++) {
            acc[s][0] = 0ull; acc[s][1] = 0ull; acc[s][2] = 0ull;
        }

        if (ecnt == 8) {
            const ulonglong2* pb = (const ulonglong2*)(rbf + (size_t)e0 * 64);
#pragma unroll 4
            for (int kb = 0; kb < 16; kb++) {
                u64 w00 = sWt64[wtb0 + 2 * kb], w01_ = sWt64[wtb0 + 2 * kb + 1];
                u64 w10 = sWt64[wtb1 + 2 * kb], w11 = sWt64[wtb1 + 2 * kb + 1];
                u64 w20 = sWt64[wtb2 + 2 * kb], w21 = sWt64[wtb2 + 2 * kb + 1];
#pragma unroll
                for (int s = 0; s < 8; s++) {
                    ulonglong2 a = __ldg(&pb[s * 16 + kb]);
                    acc[s][0] = ffma2(a.x, w00, acc[s][0]);
                    acc[s][1] = ffma2(a.x, w10, acc[s][1]);
                    acc[s][2] = ffma2(a.x, w20, acc[s][2]);
                    acc[s][0] = ffma2(a.y, w01_, acc[s][0]);
                    acc[s][1] = ffma2(a.y, w11, acc[s][1]);
                    acc[s][2] = ffma2(a.y, w21, acc[s][2]);
                }
            }
        } else {
            const ulonglong2* pbs[8];
#pragma unroll
            for (int s = 0; s < 8; s++)
                pbs[s] = (const ulonglong2*)(rbf + (size_t)min(e0 + s, E - 1) * 64);
            for (int kb = 0; kb < 16; kb++) {
                u64 w00 = sWt64[wtb0 + 2 * kb], w01_ = sWt64[wtb0 + 2 * kb + 1];
                u64 w10 = sWt64[wtb1 + 2 * kb], w11 = sWt64[wtb1 + 2 * kb + 1];
                u64 w20 = sWt64[wtb2 + 2 * kb], w21 = sWt64[wtb2 + 2 * kb + 1];
#pragma unroll
                for (int s = 0; s < 8; s++) {
                    ulonglong2 a = __ldg(&pbs[s][kb]);
                    acc[s][0] = ffma2(a.x, w00, acc[s][0]);
                    acc[s][1] = ffma2(a.x, w10, acc[s][1]);
                    acc[s][2] = ffma2(a.x, w20, acc[s][2]);
                    acc[s][0] = ffma2(a.y, w01_, acc[s][0]);
                    acc[s][1] = ffma2(a.y, w11, acc[s][1]);
                    acc[s][2] = ffma2(a.y, w21, acc[s][2]);
                }
            }
        }

        // ---------- epilogue: per edge, this warp handles its h-half ----------
        for (int s = 0; s < ecnt; s++) {
            int e = e0 + s;
            int jn = __ldg(&eidx[e]), in = __ldg(&eidx[E + e]);
            const ulonglong2* gg = (const ulonglong2*)(g_geom + (size_t)e * 8);
            ulonglong2 gA = __ldg(gg), gB = __ldg(gg + 1);
            u64 gp0 = gA.x, gp1 = gA.y, gp2 = gB.x, gp3 = gB.y;
            float ud0 = __ldg(&ud[e * 3 + 0]);
            float ud1 = __ldg(&ud[e * 3 + 1]);
            float ud2 = __ldg(&ud[e * 3 + 2]);

            float x[3];
#pragma unroll
            for (int j = 0; j < 3; j++) {
                u64 g = mul2(gp0, wiv[j][0]);
                g = ffma2(gp1, wiv[j][1], g);
                g = ffma2(gp2, wiv[j][2], g);
                g = ffma2(gp3, wiv[j][3], g);
                float glo, ghi; upk2(g, glo, ghi);
                float gate = glo + ghi + binv[j];
                float sg = __fdividef(gate, 1.0f + __expf(-gate)) * (1.0f / 0.6f);
                float f = 1.0f + tanh_fast(sg);
                float alo, ahi; upk2(acc[s][j], alo, ahi);
                float rh = alo + ahi + bedg[j];
                float sp = __ldg(&g_sproj[(size_t)jn * 192 + c0 + 64 * j]);
                x[j] = sp * rh * f * inv_sqrt3;
            }

            xw[lane] = x[0];       // x1 (local h = lane)
            xw[32 + lane] = x[1];  // x2
            xw[64 + lane] = x[2];  // x3
            __syncwarp();

            if (lane < 8) {
                const float4 x3v = *(const float4*)&xw[64 + 4 * lane];
                red4(&out[(size_t)in * 64 + hb + 4 * lane],
                     x3v.x, x3v.y, x3v.z, x3v.w);
            }
            if (lane < 24) {
                int d = lane >> 3, r = lane & 7;
                float udd = (d == 0) ? ud0 : (d == 1) ? ud1 : ud2;
                float4 f1 = *(const float4*)&xw[4 * r];
                float4 f2 = *(const float4*)&xw[32 + 4 * r];
                const float4 nvv =
                    __ldg((const float4*)(nv + (size_t)jn * 192 + d * 64 + hb + 4 * r));
                red4(&outv[(size_t)in * 192 + d * 64 + hb + 4 * r],
                     (f1.x * nvv.x + f2.x * udd) * ish,
                     (f1.y * nvv.y + f2.y * udd) * ish,
                     (f1.z * nvv.z + f2.z * udd) * ish,
                     (f1.w * nvv.w + f2.w * udd) * ish);
            }
            __syncwarp();
        }
    }
}

// ================= launch =================
extern "C" void kernel_launch(void* const* d_in, const int* in_sizes, int n_in,
                              void* d_out, int out_size) {
    const float* node_scalar = (const float*)d_in[0];
    const float* node_vector = (const float*)d_in[1];
    const float* edge_rbf    = (const float*)d_in[2];
    const float* edge_udiff  = (const float*)d_in[3];
    const int*   edge_index  = (const int*)d_in[4];
    const float* W_edge      = (const float*)d_in[5];
    const float* b_edge      = (const float*)d_in[6];
    const float* W_x1        = (const float*)d_in[7];
    const float* b_x1        = (const float*)d_in[8];
    const float* W_x2        = (const float*)d_in[9];
    const float* b_x2        = (const float*)d_in[10];
    const float* ln_g        = (const float*)d_in[11];
    const float* ln_b        = (const float*)d_in[12];
    const float* W_inv       = (const float*)d_in[13];
    const float* b_inv       = (const float*)d_in[14];

    int N = in_sizes[0] / 64;
    int E = in_sizes[3] / 3;
    float* out = (float*)d_out;

    int smem_main = 192 * 66 * 4 + 8 * 128 * 4;  // 49.5KB + 4KB
    cudaFuncSetAttribute(k_main, cudaFuncAttributeMaxDynamicSharedMemorySize,
                         smem_main);

    k_zero<<<1024, 256>>>((float4*)out, out_size / 4, N);
    k_refaccum<<<(E + 255) / 256, 256>>>(edge_udiff, edge_index, E);
    k_refvec<<<(N + 255) / 256, 256>>>(N);
    k_sproj<<<296, 256>>>(node_scalar, W_x1, b_x1, W_x2, b_x2, N);
    k_geom<<<(E + 255) / 256, 256>>>(edge_udiff, edge_index, ln_g, ln_b, E);
    k_main<<<296, 256, smem_main>>>(edge_rbf, edge_udiff, edge_index, W_edge,
                                    b_edge, W_inv, b_inv, node_vector, out, N, E);
}